// round 1
// baseline (speedup 1.0000x reference)
#include <cuda_runtime.h>
#include <cuda_bf16.h>
#include <math.h>

// Problem constants
#define BB 4
#define SS 1024
#define DD 1024
#define NH 16
#define DKH 64
#define BH (BB*NH)   // 64

// ---------------- device scratch (no allocs allowed) ----------------
__device__ float g_q[BB*NH*SS*DKH];        // [b,h,s,dk]  16MB
__device__ float g_k[BB*NH*SS*DKH];
__device__ float g_v[BB*NH*SS*DKH];
__device__ float g_scores[(size_t)BH*SS*SS];  // raw scaled scores, 256MB
__device__ float g_probs[(size_t)BH*SS*SS];   // biased softmax probs, 256MB
__device__ float g_ctx[BB*SS*DD];          // [b,s,d] 16MB
__device__ float g_res[BB*SS*DD];          // residual sum, 16MB

// ---------------- reductions ----------------
__device__ __forceinline__ float warpMax(float v){
    #pragma unroll
    for (int o=16;o;o>>=1) v = fmaxf(v, __shfl_xor_sync(0xffffffffu, v, o));
    return v;
}
__device__ __forceinline__ float warpSum(float v){
    #pragma unroll
    for (int o=16;o;o>>=1) v += __shfl_xor_sync(0xffffffffu, v, o);
    return v;
}
__device__ __forceinline__ float blockMax(float v, float* sh){
    v = warpMax(v);
    int w = threadIdx.x >> 5, l = threadIdx.x & 31;
    if (l == 0) sh[w] = v;
    __syncthreads();
    float r = sh[0];
    #pragma unroll
    for (int i=1;i<8;i++) r = fmaxf(r, sh[i]);
    __syncthreads();
    return r;
}
__device__ __forceinline__ float blockSum(float v, float* sh){
    v = warpSum(v);
    int w = threadIdx.x >> 5, l = threadIdx.x & 31;
    if (l == 0) sh[w] = v;
    __syncthreads();
    float r = sh[0];
    #pragma unroll
    for (int i=1;i<8;i++) r += sh[i];
    __syncthreads();
    return r;
}

// ---------------- 128x128x8 NT SGEMM (A[M,K], B[N,K], both K-major) ---------
// MODE 0: QKV projection: C written in head layout [b,h,s,dk], + bias[col]
// MODE 1: scores: per-blockIdx.z (bh) GEMM, C = acc * 0.125
// MODE 2: output projection: C = acc + bias[col] + resid[row*N+col]
template<int MODE>
__global__ void __launch_bounds__(256)
gemm_nt(const float* __restrict__ A, const float* __restrict__ Bm,
        const float* __restrict__ bias, const float* __restrict__ resid,
        float* __restrict__ C, int M, int N, int K)
{
    constexpr int BM=128, BN=128, BK=8;
    __shared__ float As[BK][BM];
    __shared__ float Bs[BK][BN];

    if (MODE == 1) {
        size_t z = blockIdx.z;
        A  += z * (size_t)M * K;
        Bm += z * (size_t)N * K;
        C  += z * (size_t)M * N;
    }

    int tid = threadIdx.x;
    int by = blockIdx.y, bx = blockIdx.x;
    int lr = tid >> 1;           // 0..127
    int lc = (tid & 1) << 2;     // 0 or 4

    const float* Ab = A  + (size_t)(by*BM + lr) * K + lc;
    const float* Bb = Bm + (size_t)(bx*BN + lr) * K + lc;

    int ty = tid >> 4, tx = tid & 15;
    float acc[8][8];
    #pragma unroll
    for (int i=0;i<8;i++)
        #pragma unroll
        for (int j=0;j<8;j++) acc[i][j] = 0.f;

    for (int k0 = 0; k0 < K; k0 += BK) {
        float4 a = *(const float4*)(Ab + k0);
        float4 b = *(const float4*)(Bb + k0);
        As[lc+0][lr]=a.x; As[lc+1][lr]=a.y; As[lc+2][lr]=a.z; As[lc+3][lr]=a.w;
        Bs[lc+0][lr]=b.x; Bs[lc+1][lr]=b.y; Bs[lc+2][lr]=b.z; Bs[lc+3][lr]=b.w;
        __syncthreads();
        #pragma unroll
        for (int kk=0; kk<BK; kk++) {
            float ar[8], br[8];
            #pragma unroll
            for (int i=0;i<8;i++) ar[i]=As[kk][ty*8+i];
            #pragma unroll
            for (int j=0;j<8;j++) br[j]=Bs[kk][tx*8+j];
            #pragma unroll
            for (int i=0;i<8;i++)
                #pragma unroll
                for (int j=0;j<8;j++)
                    acc[i][j] = fmaf(ar[i], br[j], acc[i][j]);
        }
        __syncthreads();
    }

    #pragma unroll
    for (int i=0;i<8;i++) {
        int row = by*BM + ty*8 + i;
        #pragma unroll
        for (int j=0;j<8;j++) {
            int col = bx*BN + tx*8 + j;
            float v = acc[i][j];
            if (MODE == 0) {
                v += bias[col];
                int b = row >> 10, s = row & 1023;
                int h = col >> 6,  dd = col & 63;
                C[((((size_t)b*NH + h) << 10) + s)*DKH + dd] = v;
            } else if (MODE == 1) {
                C[(size_t)row * N + col] = v * 0.125f;
            } else {
                size_t idx = (size_t)row * N + col;
                C[idx] = v + bias[col] + resid[idx];
            }
        }
    }
}

// ---------------- PV: per-bh  P[1024,1024] @ V[1024,64] -> ctx[b,s,h*64+n] ---
__global__ void __launch_bounds__(256)
pv_gemm(const float* __restrict__ P, const float* __restrict__ V,
        float* __restrict__ ctx)
{
    constexpr int BM=128, BN=64, BK=16;
    __shared__ float As[BK][BM];
    __shared__ float Bs[BK][BN];

    int bh = blockIdx.z;
    const float* Pb = P + ((size_t)bh << 20);
    const float* Vb = V + ((size_t)bh << 16);   // 1024*64
    int tid = threadIdx.x;
    int by = blockIdx.y;

    int ty = tid >> 4, tx = tid & 15;
    float acc[8][4];
    #pragma unroll
    for (int i=0;i<8;i++)
        #pragma unroll
        for (int j=0;j<4;j++) acc[i][j]=0.f;

    int bk = tid >> 4, bn = (tid & 15) << 2;

    for (int k0=0; k0<SS; k0+=BK) {
        #pragma unroll
        for (int r=0;r<2;r++) {
            int idx = tid + (r<<8);
            int row = idx >> 2, seg = (idx & 3) << 2;
            float4 a = *(const float4*)&Pb[(size_t)(by*BM+row)*SS + k0 + seg];
            As[seg+0][row]=a.x; As[seg+1][row]=a.y; As[seg+2][row]=a.z; As[seg+3][row]=a.w;
        }
        float4 b = *(const float4*)&Vb[(size_t)(k0+bk)*DKH + bn];
        *(float4*)&Bs[bk][bn] = b;
        __syncthreads();
        #pragma unroll
        for (int kk=0;kk<BK;kk++){
            float ar[8], br[4];
            #pragma unroll
            for (int i=0;i<8;i++) ar[i]=As[kk][ty*8+i];
            #pragma unroll
            for (int j=0;j<4;j++) br[j]=Bs[kk][tx*4+j];
            #pragma unroll
            for (int i=0;i<8;i++)
                #pragma unroll
                for (int j=0;j<4;j++)
                    acc[i][j] = fmaf(ar[i], br[j], acc[i][j]);
        }
        __syncthreads();
    }

    int b = bh >> 4, h = bh & 15;
    #pragma unroll
    for (int i=0;i<8;i++) {
        int s = by*BM + ty*8 + i;
        int n = tx*4;
        float4 o = make_float4(acc[i][0], acc[i][1], acc[i][2], acc[i][3]);
        *(float4*)&ctx[(((size_t)b << 10) + s)*DD + h*DKH + n] = o;
    }
}

// ---------------- biased softmax over raw scores -> probs --------------------
__global__ void __launch_bounds__(256)
softmax_bias(const float* __restrict__ Sc, float* __restrict__ P,
             const int* __restrict__ ts_ptr)
{
    __shared__ float red[8];
    int bh  = blockIdx.y;
    int row = blockIdx.x;
    const float* src = Sc + ((size_t)bh << 20) + ((size_t)row << 10);
    float*       dst = P  + ((size_t)bh << 20) + ((size_t)row << 10);
    bool ub = (ts_ptr[0] < 8) && (row < 64);
    int tid = threadIdx.x;

    float v[4];
    #pragma unroll
    for (int j=0;j<4;j++) {
        int c = tid + (j<<8);
        float x = src[c];
        if (ub && c < 64) x += 0.1f / (fabsf((float)(row - c)) + 1.0f);
        v[j] = x;
    }
    float m = fmaxf(fmaxf(v[0],v[1]), fmaxf(v[2],v[3]));
    m = blockMax(m, red);
    float s = 0.f;
    #pragma unroll
    for (int j=0;j<4;j++) { v[j] = __expf(v[j]-m); s += v[j]; }
    s = blockSum(s, red);
    float inv = 1.0f / s;
    #pragma unroll
    for (int j=0;j<4;j++) dst[tid + (j<<8)] = v[j]*inv;
}

// ---------------- attn_weights: head-mean of UNbiased softmax ----------------
__global__ void __launch_bounds__(256)
attn_weights(const float* __restrict__ Sc, float* __restrict__ out2)
{
    __shared__ float red[8];
    int b   = blockIdx.y;
    int row = blockIdx.x;
    int tid = threadIdx.x;
    float a[4] = {0.f,0.f,0.f,0.f};

    for (int h=0; h<NH; h++) {
        const float* src = Sc + (((size_t)(b*NH + h)) << 20) + ((size_t)row << 10);
        float v[4];
        #pragma unroll
        for (int j=0;j<4;j++) v[j] = src[tid + (j<<8)];
        float m = fmaxf(fmaxf(v[0],v[1]), fmaxf(v[2],v[3]));
        m = blockMax(m, red);
        float s = 0.f;
        #pragma unroll
        for (int j=0;j<4;j++) { v[j] = __expf(v[j]-m); s += v[j]; }
        s = blockSum(s, red);
        float inv = 1.0f / s;
        #pragma unroll
        for (int j=0;j<4;j++) a[j] += v[j]*inv;
    }
    float* dst = out2 + (((size_t)b) << 20) + ((size_t)row << 10);
    #pragma unroll
    for (int j=0;j<4;j++) dst[tid + (j<<8)] = a[j] * (1.0f/16.0f);
}

// ---------------- LayerNorm --------------------------------------------------
__global__ void __launch_bounds__(256)
layernorm(const float* __restrict__ R, const float* __restrict__ gamma,
          const float* __restrict__ beta, float* __restrict__ out)
{
    __shared__ float red[8];
    int row = blockIdx.x;
    int tid = threadIdx.x;
    const float* src = R + ((size_t)row << 10);
    float v[4];
    #pragma unroll
    for (int j=0;j<4;j++) v[j] = src[tid + (j<<8)];
    float s = v[0]+v[1]+v[2]+v[3];
    s = blockSum(s, red);
    float mu = s * (1.0f/1024.0f);
    float q = 0.f;
    #pragma unroll
    for (int j=0;j<4;j++) { float d = v[j]-mu; q += d*d; }
    q = blockSum(q, red);
    float inv = rsqrtf(q * (1.0f/1024.0f) + 1e-5f);
    #pragma unroll
    for (int j=0;j<4;j++) {
        int c = tid + (j<<8);
        out[((size_t)row << 10) + c] = (v[j]-mu)*inv*gamma[c] + beta[c];
    }
}

// ---------------- launch -----------------------------------------------------
extern "C" void kernel_launch(void* const* d_in, const int* in_sizes, int n_in,
                              void* d_out, int out_size)
{
    const float* x  = (const float*)d_in[0];
    const int*   ts = (const int*)  d_in[1];
    const float* Wq = (const float*)d_in[2];
    const float* bq = (const float*)d_in[3];
    const float* Wk = (const float*)d_in[4];
    const float* bk = (const float*)d_in[5];
    const float* Wv = (const float*)d_in[6];
    const float* bv = (const float*)d_in[7];
    const float* Wo = (const float*)d_in[8];
    const float* bo = (const float*)d_in[9];
    const float* ga = (const float*)d_in[10];
    const float* be = (const float*)d_in[11];

    float* out1 = (float*)d_out;                       // normed [4,32,32,1024]
    float* out2 = out1 + (size_t)BB*SS*DD;             // attn_weights [4,1024,1024]

    void *pq, *pk, *pv, *psc, *ppr, *pctx, *pres;
    cudaGetSymbolAddress(&pq,  g_q);
    cudaGetSymbolAddress(&pk,  g_k);
    cudaGetSymbolAddress(&pv,  g_v);
    cudaGetSymbolAddress(&psc, g_scores);
    cudaGetSymbolAddress(&ppr, g_probs);
    cudaGetSymbolAddress(&pctx,g_ctx);
    cudaGetSymbolAddress(&pres,g_res);

    dim3 blk(256);

    // QKV projections: [4096,1024] = x @ W^T + b, written in head layout
    gemm_nt<0><<<dim3(8,32), blk>>>(x, Wq, bq, nullptr, (float*)pq, BB*SS, DD, DD);
    gemm_nt<0><<<dim3(8,32), blk>>>(x, Wk, bk, nullptr, (float*)pk, BB*SS, DD, DD);
    gemm_nt<0><<<dim3(8,32), blk>>>(x, Wv, bv, nullptr, (float*)pv, BB*SS, DD, DD);

    // Raw scaled scores per (b,h): [1024,1024] = Q @ K^T * 0.125
    gemm_nt<1><<<dim3(8,8,BH), blk>>>((const float*)pq, (const float*)pk,
                                      nullptr, nullptr, (float*)psc, SS, SS, DKH);

    // Biased softmax -> probs
    softmax_bias<<<dim3(SS,BH), blk>>>((const float*)psc, (float*)ppr, ts);

    // ctx = probs @ V, written flat [b,s,d]
    pv_gemm<<<dim3(1,8,BH), blk>>>((const float*)ppr, (const float*)pv, (float*)pctx);

    // out projection + bias + residual
    gemm_nt<2><<<dim3(8,32), blk>>>((const float*)pctx, Wo, bo, x,
                                    (float*)pres, BB*SS, DD, DD);

    // LayerNorm -> output 1
    layernorm<<<dim3(BB*SS), blk>>>((const float*)pres, ga, be, out1);

    // Head-mean unbiased softmax -> output 2
    attn_weights<<<dim3(SS,BB), blk>>>((const float*)psc, out2);
}

// round 2
// speedup vs baseline: 3.2986x; 3.2986x over previous
#include <cuda_runtime.h>
#include <cuda_bf16.h>
#include <cstdint>
#include <math.h>

// Problem constants
#define BB 4
#define SS 1024
#define DD 1024
#define NH 16
#define DKH 64
#define BHN (BB*NH)   // 64

// ---------------- device scratch (no allocs allowed) ----------------
__device__ float g_q[BB*NH*SS*DKH];           // [b,h,s,dk]  16MB
__device__ float g_k[BB*NH*SS*DKH];
__device__ float g_v[BB*NH*SS*DKH];
__device__ float g_scores[(size_t)BHN*SS*SS]; // raw scaled scores, 256MB
__device__ float g_probs[(size_t)BHN*SS*SS];  // biased softmax probs, 256MB
__device__ float g_ctx[BB*SS*DD];             // [b,s,d] 16MB
__device__ float g_res[BB*SS*DD];             // residual sum, 16MB

// ---------------- reductions ----------------
__device__ __forceinline__ float warpMax(float v){
    #pragma unroll
    for (int o=16;o;o>>=1) v = fmaxf(v, __shfl_xor_sync(0xffffffffu, v, o));
    return v;
}
__device__ __forceinline__ float warpSum(float v){
    #pragma unroll
    for (int o=16;o;o>>=1) v += __shfl_xor_sync(0xffffffffu, v, o);
    return v;
}
__device__ __forceinline__ float blockMax(float v, float* sh){
    v = warpMax(v);
    int w = threadIdx.x >> 5, l = threadIdx.x & 31;
    if (l == 0) sh[w] = v;
    __syncthreads();
    float r = sh[0];
    #pragma unroll
    for (int i=1;i<8;i++) r = fmaxf(r, sh[i]);
    __syncthreads();
    return r;
}
__device__ __forceinline__ float blockSum(float v, float* sh){
    v = warpSum(v);
    int w = threadIdx.x >> 5, l = threadIdx.x & 31;
    if (l == 0) sh[w] = v;
    __syncthreads();
    float r = sh[0];
    #pragma unroll
    for (int i=1;i<8;i++) r += sh[i];
    __syncthreads();
    return r;
}

// ---------------- tensor-core helpers ----------------
__device__ __forceinline__ void mma_tf32(float* d, const uint32_t* a, const uint32_t* b){
    asm volatile(
        "mma.sync.aligned.m16n8k8.row.col.f32.tf32.tf32.f32 "
        "{%0,%1,%2,%3}, {%4,%5,%6,%7}, {%8,%9}, {%0,%1,%2,%3};\n"
        : "+f"(d[0]), "+f"(d[1]), "+f"(d[2]), "+f"(d[3])
        : "r"(a[0]), "r"(a[1]), "r"(a[2]), "r"(a[3]),
          "r"(b[0]), "r"(b[1]));
}
__device__ __forceinline__ void cpasync16(uint32_t s, const void* g){
    asm volatile("cp.async.cg.shared.global [%0], [%1], 16;\n" :: "r"(s), "l"(g));
}
__device__ __forceinline__ uint32_t smem_u32(const void* p){
    return (uint32_t)__cvta_generic_to_shared(p);
}

// =====================================================================
// Tensor-core tf32 GEMM.
//  A [M,K] row-major. B: BT=true -> [N,K] row-major (NT); BT=false -> [K,N] (NN).
//  MODE 0: QKV proj -> head-layout scatter + bias
//  MODE 1: scores  (batched over z=bh) -> *0.125
//  MODE 2: out proj -> + bias + residual (flat)
//  MODE 3: PV (batched over z=bh) -> ctx[b,s, h*64+col]
// =====================================================================
template<int BM, int BN, int WARPS_M, int WARPS_N, int WM, int WN, bool BT, int MODE>
__global__ void __launch_bounds__(WARPS_M*WARPS_N*32)
mma_gemm(const float* __restrict__ A, const float* __restrict__ Bg,
         const float* __restrict__ bias, const float* __restrict__ resid,
         float* __restrict__ C, int M, int N, int K)
{
    constexpr int BK = 32, S = 36;                 // smem row stride (pad 4)
    constexpr int T  = WARPS_M*WARPS_N*32;
    constexpr int MT = WM/16, NTL = WN/8;

    extern __shared__ float sm[];
    float* As = sm;                 // [2][BM][S]
    float* Bs = sm + 2*BM*S;        // [2][BN][S]

    const int z = blockIdx.z;
    if (MODE == 1) { A += (size_t)z*M*K; Bg += (size_t)z*N*K; C += (size_t)z << 20; }
    if (MODE == 3) {
        A += (size_t)z << 20;                      // probs
        Bg += (size_t)z << 16;                     // V per-bh [1024,64]
        C += ((size_t)(z >> 4) << 20) + (size_t)(z & 15)*64;   // ctx[b, :, h*64]
    }

    const int tid = threadIdx.x;
    const int bm0 = blockIdx.y*BM, bn0 = blockIdx.x*BN;

    constexpr int ACH = BM*(BK/16/1)*2/ (T/4);     // placeholder (recomputed below)
    (void)sizeof(char[ACH>=0?1:1]);
    constexpr int A_CH = (BM*(BK/4))/T;            // 16B chunks / thread
    constexpr int B_CH = BT ? (BN*(BK/4))/T : 0;
    constexpr int B_F4 = BT ? 0 : ((BK*BN/4)/T);   // float4 / thread (NN)

    auto loadA = [&](int buf, int k0){
        #pragma unroll
        for (int i = 0; i < A_CH; i++){
            int id = tid + i*T;
            int r = id >> 3, ks = (id & 7)*4;
            cpasync16(smem_u32(&As[buf*BM*S + r*S + ks]),
                      A + (size_t)(bm0 + r)*K + k0 + ks);
        }
    };
    auto loadB = [&](int buf, int k0){
        if (BT) {
            #pragma unroll
            for (int i = 0; i < B_CH; i++){
                int id = tid + i*T;
                int r = id >> 3, ks = (id & 7)*4;
                cpasync16(smem_u32(&Bs[buf*BN*S + r*S + ks]),
                          Bg + (size_t)(bn0 + r)*K + k0 + ks);
            }
        } else {
            #pragma unroll
            for (int i = 0; i < B_F4; i++){
                int id = tid + i*T;
                int k = id >> 4, n4 = (id & 15)*4;   // N=64 -> 16 float4 per k-row
                float4 v = *(const float4*)(Bg + (size_t)(k0 + k)*N + n4);
                float* d = &Bs[buf*BN*S + n4*S + k];
                d[0]   = v.x; d[S]   = v.y; d[2*S] = v.z; d[3*S] = v.w;
            }
        }
    };

    const int lane = tid & 31, g = lane >> 2, tg = lane & 3;
    const int warp = tid >> 5;
    const int wm = (warp / WARPS_N) * WM, wn = (warp % WARPS_N) * WN;

    float acc[MT][NTL][4];
    #pragma unroll
    for (int i=0;i<MT;i++)
        #pragma unroll
        for (int j=0;j<NTL;j++)
            #pragma unroll
            for (int r=0;r<4;r++) acc[i][j][r] = 0.f;

    const int nt = K / BK;
    loadA(0, 0); loadB(0, 0);
    asm volatile("cp.async.commit_group;\n");

    for (int it = 0; it < nt; it++){
        int buf = it & 1;
        if (it + 1 < nt) {
            loadA(buf^1, (it+1)*BK); loadB(buf^1, (it+1)*BK);
            asm volatile("cp.async.commit_group;\n");
            asm volatile("cp.async.wait_group 1;\n");
        } else {
            asm volatile("cp.async.wait_group 0;\n");
        }
        __syncthreads();

        const float* Ab = As + buf*BM*S;
        const float* Bb = Bs + buf*BN*S;
        #pragma unroll
        for (int c = 0; c < BK/8; c++){
            uint32_t af[MT][4], bf[NTL][2];
            #pragma unroll
            for (int i = 0; i < MT; i++){
                const float* ap = Ab + (wm + i*16 + g)*S + c*8 + tg;
                af[i][0] = __float_as_uint(ap[0]);
                af[i][1] = __float_as_uint(ap[8*S]);
                af[i][2] = __float_as_uint(ap[4]);
                af[i][3] = __float_as_uint(ap[8*S + 4]);
            }
            #pragma unroll
            for (int j = 0; j < NTL; j++){
                const float* bp = Bb + (wn + j*8 + g)*S + c*8 + tg;
                bf[j][0] = __float_as_uint(bp[0]);
                bf[j][1] = __float_as_uint(bp[4]);
            }
            #pragma unroll
            for (int i = 0; i < MT; i++)
                #pragma unroll
                for (int j = 0; j < NTL; j++)
                    mma_tf32(acc[i][j], af[i], bf[j]);
        }
        __syncthreads();
    }

    // ---------------- epilogue ----------------
    #pragma unroll
    for (int i = 0; i < MT; i++){
        #pragma unroll
        for (int rr = 0; rr < 2; rr++){
            int row = bm0 + wm + i*16 + g + rr*8;
            #pragma unroll
            for (int j = 0; j < NTL; j++){
                int col = bn0 + wn + j*8 + 2*tg;
                float vx = acc[i][j][rr*2 + 0];
                float vy = acc[i][j][rr*2 + 1];
                if (MODE == 0) {
                    vx += bias[col]; vy += bias[col+1];
                    int b = row >> 10, s = row & 1023;
                    int h = col >> 6, dd = col & 63;
                    float2 o = make_float2(vx, vy);
                    *(float2*)&C[((size_t)(b*NH + h) << 16) + s*DKH + dd] = o;
                } else if (MODE == 1) {
                    float2 o = make_float2(vx*0.125f, vy*0.125f);
                    *(float2*)&C[((size_t)row << 10) + col] = o;
                } else if (MODE == 2) {
                    size_t idx = (size_t)row*N + col;
                    float2 r2 = *(const float2*)&resid[idx];
                    float2 o = make_float2(vx + bias[col] + r2.x,
                                           vy + bias[col+1] + r2.y);
                    *(float2*)&C[idx] = o;
                } else {  // MODE 3
                    float2 o = make_float2(vx, vy);
                    *(float2*)&C[((size_t)row << 10) + col] = o;
                }
            }
        }
    }
}

// ---------------- fused softmax: biased probs + head-mean unbiased ----------
__global__ void __launch_bounds__(256)
softmax_fused(const float* __restrict__ Sc, float* __restrict__ P,
              float* __restrict__ out2, const int* __restrict__ ts_ptr)
{
    __shared__ float red[8];
    const int b   = blockIdx.y;
    const int row = blockIdx.x;
    const int tid = threadIdx.x;
    const bool dobias = (ts_ptr[0] < 8) && (row < 64);

    float accw[4] = {0.f, 0.f, 0.f, 0.f};

    for (int h = 0; h < NH; h++){
        size_t off = (((size_t)(b*NH + h)) << 20) + ((size_t)row << 10);
        const float* src = Sc + off;
        float* dst = P + off;

        float v[4];
        #pragma unroll
        for (int j = 0; j < 4; j++) v[j] = src[tid + (j << 8)];

        // unbiased softmax (for attn_weights)
        float m = fmaxf(fmaxf(v[0], v[1]), fmaxf(v[2], v[3]));
        m = blockMax(m, red);
        float e[4], s = 0.f;
        #pragma unroll
        for (int j = 0; j < 4; j++){ e[j] = __expf(v[j] - m); s += e[j]; }
        s = blockSum(s, red);
        float inv = 1.0f / s;
        #pragma unroll
        for (int j = 0; j < 4; j++) accw[j] += e[j]*inv;

        if (dobias) {
            float vb[4];
            #pragma unroll
            for (int j = 0; j < 4; j++){
                int c = tid + (j << 8);
                vb[j] = v[j] + ((c < 64) ? 0.1f / (fabsf((float)(row - c)) + 1.0f) : 0.f);
            }
            float m2 = fmaxf(fmaxf(vb[0], vb[1]), fmaxf(vb[2], vb[3]));
            m2 = blockMax(m2, red);
            float s2 = 0.f, eb[4];
            #pragma unroll
            for (int j = 0; j < 4; j++){ eb[j] = __expf(vb[j] - m2); s2 += eb[j]; }
            s2 = blockSum(s2, red);
            float inv2 = 1.0f / s2;
            #pragma unroll
            for (int j = 0; j < 4; j++) dst[tid + (j << 8)] = eb[j]*inv2;
        } else {
            #pragma unroll
            for (int j = 0; j < 4; j++) dst[tid + (j << 8)] = e[j]*inv;
        }
    }

    float* d2 = out2 + (((size_t)b) << 20) + ((size_t)row << 10);
    #pragma unroll
    for (int j = 0; j < 4; j++) d2[tid + (j << 8)] = accw[j] * (1.0f/16.0f);
}

// ---------------- LayerNorm --------------------------------------------------
__global__ void __launch_bounds__(256)
layernorm(const float* __restrict__ R, const float* __restrict__ gamma,
          const float* __restrict__ beta, float* __restrict__ out)
{
    __shared__ float red[8];
    int row = blockIdx.x;
    int tid = threadIdx.x;
    const float* src = R + ((size_t)row << 10);
    float v[4];
    #pragma unroll
    for (int j=0;j<4;j++) v[j] = src[tid + (j<<8)];
    float s = v[0]+v[1]+v[2]+v[3];
    s = blockSum(s, red);
    float mu = s * (1.0f/1024.0f);
    float q = 0.f;
    #pragma unroll
    for (int j=0;j<4;j++) { float d = v[j]-mu; q += d*d; }
    q = blockSum(q, red);
    float inv = rsqrtf(q * (1.0f/1024.0f) + 1e-5f);
    #pragma unroll
    for (int j=0;j<4;j++) {
        int c = tid + (j<<8);
        out[((size_t)row << 10) + c] = (v[j]-mu)*inv*gamma[c] + beta[c];
    }
}

// ---------------- launch -----------------------------------------------------
extern "C" void kernel_launch(void* const* d_in, const int* in_sizes, int n_in,
                              void* d_out, int out_size)
{
    const float* x  = (const float*)d_in[0];
    const int*   ts = (const int*)  d_in[1];
    const float* Wq = (const float*)d_in[2];
    const float* bq = (const float*)d_in[3];
    const float* Wk = (const float*)d_in[4];
    const float* bk = (const float*)d_in[5];
    const float* Wv = (const float*)d_in[6];
    const float* bv = (const float*)d_in[7];
    const float* Wo = (const float*)d_in[8];
    const float* bo = (const float*)d_in[9];
    const float* ga = (const float*)d_in[10];
    const float* be = (const float*)d_in[11];

    float* out1 = (float*)d_out;                       // normed [4,32,32,1024]
    float* out2 = out1 + (size_t)BB*SS*DD;             // attn_weights [4,1024,1024]

    void *pq, *pk, *pv, *psc, *ppr, *pctx, *pres;
    cudaGetSymbolAddress(&pq,  g_q);
    cudaGetSymbolAddress(&pk,  g_k);
    cudaGetSymbolAddress(&pv,  g_v);
    cudaGetSymbolAddress(&psc, g_scores);
    cudaGetSymbolAddress(&ppr, g_probs);
    cudaGetSymbolAddress(&pctx,g_ctx);
    cudaGetSymbolAddress(&pres,g_res);

    // GEMM kernel instantiations
    auto kproj   = mma_gemm<128,128,2,2,64,64,true ,0>;
    auto kscore  = mma_gemm<128,128,2,2,64,64,true ,1>;
    auto koproj  = mma_gemm<128,128,2,2,64,64,true ,2>;
    auto kpv     = mma_gemm<128, 64,4,1,32,64,false,3>;

    const int SM_BIG = 2*(128+128)*36*4;   // 73728 B
    const int SM_PV  = 2*(128+ 64)*36*4;   // 55296 B
    cudaFuncSetAttribute((const void*)kproj,  cudaFuncAttributeMaxDynamicSharedMemorySize, SM_BIG);
    cudaFuncSetAttribute((const void*)kscore, cudaFuncAttributeMaxDynamicSharedMemorySize, SM_BIG);
    cudaFuncSetAttribute((const void*)koproj, cudaFuncAttributeMaxDynamicSharedMemorySize, SM_BIG);
    cudaFuncSetAttribute((const void*)kpv,    cudaFuncAttributeMaxDynamicSharedMemorySize, SM_PV);

    dim3 blk(128);

    // QKV projections: [4096,1024] = x @ W^T + b, written in head layout
    kproj<<<dim3(8,32), blk, SM_BIG>>>(x, Wq, bq, nullptr, (float*)pq, BB*SS, DD, DD);
    kproj<<<dim3(8,32), blk, SM_BIG>>>(x, Wk, bk, nullptr, (float*)pk, BB*SS, DD, DD);
    kproj<<<dim3(8,32), blk, SM_BIG>>>(x, Wv, bv, nullptr, (float*)pv, BB*SS, DD, DD);

    // Raw scaled scores per (b,h): [1024,1024] = Q @ K^T * 0.125
    kscore<<<dim3(8,8,BHN), blk, SM_BIG>>>((const float*)pq, (const float*)pk,
                                           nullptr, nullptr, (float*)psc, SS, SS, DKH);

    // Fused: biased softmax -> probs, head-mean unbiased softmax -> out2
    softmax_fused<<<dim3(SS,BB), 256>>>((const float*)psc, (float*)ppr, out2, ts);

    // ctx = probs @ V, written flat [b,s,d]
    kpv<<<dim3(1,8,BHN), blk, SM_PV>>>((const float*)ppr, (const float*)pv,
                                       nullptr, nullptr, (float*)pctx, SS, DKH, SS);

    // out projection + bias + residual
    koproj<<<dim3(8,32), blk, SM_BIG>>>((const float*)pctx, Wo, bo, x,
                                        (float*)pres, BB*SS, DD, DD);

    // LayerNorm -> output 1
    layernorm<<<dim3(BB*SS), 256>>>((const float*)pres, ga, be, out1);
}

// round 3
// speedup vs baseline: 3.3467x; 1.0146x over previous
#include <cuda_runtime.h>
#include <cuda_bf16.h>
#include <cstdint>
#include <math.h>

// Problem constants
#define BB 4
#define SS 1024
#define DD 1024
#define NH 16
#define DKH 64
#define BHN (BB*NH)   // 64

// ---------------- device scratch (no allocs allowed) ----------------
__device__ float g_q[BB*NH*SS*DKH];                 // [b,h,s,dk]  16MB
__device__ float g_k[BB*NH*SS*DKH];
__device__ float g_v[BB*NH*SS*DKH];
__device__ __nv_bfloat16 g_pb[(size_t)BHN*SS*SS];   // biased probs bf16, 128MB
__device__ __nv_bfloat16 g_pu[(size_t)BHN*64*SS];   // unbiased probs rows<64, 8MB
__device__ float g_ctx[BB*SS*DD];                   // [b,s,d] 16MB
__device__ float g_res[BB*SS*DD];                   // residual sum, 16MB

// ---------------- reductions ----------------
__device__ __forceinline__ float warpMax(float v){
    #pragma unroll
    for (int o=16;o;o>>=1) v = fmaxf(v, __shfl_xor_sync(0xffffffffu, v, o));
    return v;
}
__device__ __forceinline__ float warpSum(float v){
    #pragma unroll
    for (int o=16;o;o>>=1) v += __shfl_xor_sync(0xffffffffu, v, o);
    return v;
}
__device__ __forceinline__ float blockSum(float v, float* sh){
    v = warpSum(v);
    int w = threadIdx.x >> 5, l = threadIdx.x & 31;
    if (l == 0) sh[w] = v;
    __syncthreads();
    float r = sh[0];
    #pragma unroll
    for (int i=1;i<8;i++) r += sh[i];
    __syncthreads();
    return r;
}

// ---------------- tensor-core helpers ----------------
__device__ __forceinline__ void mma_tf32(float* d, const uint32_t* a, const uint32_t* b){
    asm volatile(
        "mma.sync.aligned.m16n8k8.row.col.f32.tf32.tf32.f32 "
        "{%0,%1,%2,%3}, {%4,%5,%6,%7}, {%8,%9}, {%0,%1,%2,%3};\n"
        : "+f"(d[0]), "+f"(d[1]), "+f"(d[2]), "+f"(d[3])
        : "r"(a[0]), "r"(a[1]), "r"(a[2]), "r"(a[3]),
          "r"(b[0]), "r"(b[1]));
}
__device__ __forceinline__ void mma_bf16(float* d, const uint32_t* a, const uint32_t* b){
    asm volatile(
        "mma.sync.aligned.m16n8k16.row.col.f32.bf16.bf16.f32 "
        "{%0,%1,%2,%3}, {%4,%5,%6,%7}, {%8,%9}, {%0,%1,%2,%3};\n"
        : "+f"(d[0]), "+f"(d[1]), "+f"(d[2]), "+f"(d[3])
        : "r"(a[0]), "r"(a[1]), "r"(a[2]), "r"(a[3]),
          "r"(b[0]), "r"(b[1]));
}
__device__ __forceinline__ void cpasync16(uint32_t s, const void* g){
    asm volatile("cp.async.cg.shared.global [%0], [%1], 16;\n" :: "r"(s), "l"(g));
}
__device__ __forceinline__ uint32_t smem_u32(const void* p){
    return (uint32_t)__cvta_generic_to_shared(p);
}
__device__ __forceinline__ void st_bf16x4(__nv_bfloat16* dst, float4 p){
    __nv_bfloat162 a = __floats2bfloat162_rn(p.x, p.y);
    __nv_bfloat162 b = __floats2bfloat162_rn(p.z, p.w);
    uint2 u;
    u.x = *reinterpret_cast<uint32_t*>(&a);
    u.y = *reinterpret_cast<uint32_t*>(&b);
    *reinterpret_cast<uint2*>(dst) = u;
}

// =====================================================================
// tf32 GEMM for projections.
//  A [M,K] row-major, B [N,K] row-major (NT).
//  MODE 0: QKV proj -> head-layout scatter + bias
//  MODE 2: out proj -> + bias + residual (flat)
// =====================================================================
template<int MODE>
__global__ void __launch_bounds__(128)
mma_gemm(const float* __restrict__ A, const float* __restrict__ Bg,
         const float* __restrict__ bias, const float* __restrict__ resid,
         float* __restrict__ C, int M, int N, int K)
{
    constexpr int BM=128, BN=128, BK=32, S=36;
    constexpr int T=128, MT=4, NTL=8;     // 2x2 warps, 64x64 warp tiles

    extern __shared__ float sm[];
    float* As = sm;                 // [2][BM][S]
    float* Bs = sm + 2*BM*S;        // [2][BN][S]

    const int tid = threadIdx.x;
    const int bm0 = blockIdx.y*BM, bn0 = blockIdx.x*BN;

    auto loadA = [&](int buf, int k0){
        #pragma unroll
        for (int i = 0; i < 8; i++){
            int id = tid + i*T;
            int r = id >> 3, ks = (id & 7)*4;
            cpasync16(smem_u32(&As[buf*BM*S + r*S + ks]),
                      A + (size_t)(bm0 + r)*K + k0 + ks);
        }
    };
    auto loadB = [&](int buf, int k0){
        #pragma unroll
        for (int i = 0; i < 8; i++){
            int id = tid + i*T;
            int r = id >> 3, ks = (id & 7)*4;
            cpasync16(smem_u32(&Bs[buf*BN*S + r*S + ks]),
                      Bg + (size_t)(bn0 + r)*K + k0 + ks);
        }
    };

    const int lane = tid & 31, g = lane >> 2, tg = lane & 3;
    const int warp = tid >> 5;
    const int wm = (warp >> 1) * 64, wn = (warp & 1) * 64;

    float acc[MT][NTL][4];
    #pragma unroll
    for (int i=0;i<MT;i++)
        #pragma unroll
        for (int j=0;j<NTL;j++)
            #pragma unroll
            for (int r=0;r<4;r++) acc[i][j][r] = 0.f;

    const int nt = K / BK;
    loadA(0, 0); loadB(0, 0);
    asm volatile("cp.async.commit_group;\n");

    for (int it = 0; it < nt; it++){
        int buf = it & 1;
        if (it + 1 < nt) {
            loadA(buf^1, (it+1)*BK); loadB(buf^1, (it+1)*BK);
            asm volatile("cp.async.commit_group;\n");
            asm volatile("cp.async.wait_group 1;\n");
        } else {
            asm volatile("cp.async.wait_group 0;\n");
        }
        __syncthreads();

        const float* Ab = As + buf*BM*S;
        const float* Bb = Bs + buf*BN*S;
        #pragma unroll
        for (int c = 0; c < BK/8; c++){
            uint32_t af[MT][4], bf[NTL][2];
            #pragma unroll
            for (int i = 0; i < MT; i++){
                const float* ap = Ab + (wm + i*16 + g)*S + c*8 + tg;
                af[i][0] = __float_as_uint(ap[0]);
                af[i][1] = __float_as_uint(ap[8*S]);
                af[i][2] = __float_as_uint(ap[4]);
                af[i][3] = __float_as_uint(ap[8*S + 4]);
            }
            #pragma unroll
            for (int j = 0; j < NTL; j++){
                const float* bp = Bb + (wn + j*8 + g)*S + c*8 + tg;
                bf[j][0] = __float_as_uint(bp[0]);
                bf[j][1] = __float_as_uint(bp[4]);
            }
            #pragma unroll
            for (int i = 0; i < MT; i++)
                #pragma unroll
                for (int j = 0; j < NTL; j++)
                    mma_tf32(acc[i][j], af[i], bf[j]);
        }
        __syncthreads();
    }

    #pragma unroll
    for (int i = 0; i < MT; i++){
        #pragma unroll
        for (int rr = 0; rr < 2; rr++){
            int row = bm0 + wm + i*16 + g + rr*8;
            #pragma unroll
            for (int j = 0; j < NTL; j++){
                int col = bn0 + wn + j*8 + 2*tg;
                float vx = acc[i][j][rr*2 + 0];
                float vy = acc[i][j][rr*2 + 1];
                if (MODE == 0) {
                    vx += bias[col]; vy += bias[col+1];
                    int b = row >> 10, s = row & 1023;
                    int h = col >> 6, dd = col & 63;
                    float2 o = make_float2(vx, vy);
                    *(float2*)&C[((size_t)(b*NH + h) << 16) + s*DKH + dd] = o;
                } else {
                    size_t idx = (size_t)row*N + col;
                    float2 r2 = *(const float2*)&resid[idx];
                    float2 o = make_float2(vx + bias[col] + r2.x,
                                           vy + bias[col+1] + r2.y);
                    *(float2*)&C[idx] = o;
                }
            }
        }
    }
}

// =====================================================================
// FUSED: S = Q@K^T * 0.125 (tile [32,1024] in smem, fp32), then both
// softmaxes: biased probs -> g_pb (bf16, all rows), unbiased rows<64 -> g_pu.
// grid: (qtile=32, h=16, b=4), 256 threads.
// =====================================================================
#define QT 32
#define SST 1032      // S smem stride
__global__ void __launch_bounds__(256)
fused_qk_softmax(const float* __restrict__ Q, const float* __restrict__ K,
                 __nv_bfloat16* __restrict__ pb, __nv_bfloat16* __restrict__ pu,
                 const int* __restrict__ ts_ptr)
{
    extern __shared__ float sm[];
    float* Ssm = sm;                       // [32][1032]
    float* Qs  = sm + 32*SST;              // [32][68]
    float* Ks  = Qs + 32*68;               // [2][128][68]

    const int tid  = threadIdx.x;
    const int lane = tid & 31, g = lane >> 2, tg = lane & 3;
    const int w    = tid >> 5;
    const int qt   = blockIdx.x;
    const int bh   = blockIdx.z*NH + blockIdx.y;
    const size_t qkbase = (size_t)bh << 16;   // *1024*64
    const int qrow0 = qt * QT;

    // load Q tile [32][64]
    #pragma unroll
    for (int i = 0; i < 2; i++){
        int id = tid + i*256;
        int r = id >> 4, c = (id & 15) << 2;
        cpasync16(smem_u32(&Qs[r*68 + c]), Q + qkbase + (size_t)(qrow0 + r)*64 + c);
    }
    auto loadK = [&](int buf, int kr0){
        #pragma unroll
        for (int i = 0; i < 8; i++){
            int id = tid + i*256;
            int r = id >> 4, c = (id & 15) << 2;
            cpasync16(smem_u32(&Ks[(size_t)buf*128*68 + r*68 + c]),
                      K + qkbase + (size_t)(kr0 + r)*64 + c);
        }
    };
    loadK(0, 0);
    asm volatile("cp.async.commit_group;\n");

    for (int cc = 0; cc < 8; cc++){
        int buf = cc & 1;
        if (cc < 7){
            loadK(buf^1, (cc+1)*128);
            asm volatile("cp.async.commit_group;\n");
            asm volatile("cp.async.wait_group 1;\n");
        } else {
            asm volatile("cp.async.wait_group 0;\n");
        }
        __syncthreads();

        float acc[2][2][4];
        #pragma unroll
        for (int i=0;i<2;i++)
            #pragma unroll
            for (int j=0;j<2;j++)
                #pragma unroll
                for (int r=0;r<4;r++) acc[i][j][r]=0.f;

        const float* Kb = Ks + (size_t)buf*128*68;
        #pragma unroll
        for (int c = 0; c < 8; c++){
            uint32_t af[2][4], bf[2][2];
            #pragma unroll
            for (int i = 0; i < 2; i++){
                const float* ap = Qs + (i*16 + g)*68 + c*8 + tg;
                af[i][0] = __float_as_uint(ap[0]);
                af[i][1] = __float_as_uint(ap[8*68]);
                af[i][2] = __float_as_uint(ap[4]);
                af[i][3] = __float_as_uint(ap[8*68 + 4]);
            }
            #pragma unroll
            for (int j = 0; j < 2; j++){
                const float* bp = Kb + (w*16 + j*8 + g)*68 + c*8 + tg;
                bf[j][0] = __float_as_uint(bp[0]);
                bf[j][1] = __float_as_uint(bp[4]);
            }
            #pragma unroll
            for (int i = 0; i < 2; i++)
                #pragma unroll
                for (int j = 0; j < 2; j++)
                    mma_tf32(acc[i][j], af[i], bf[j]);
        }
        // store S tile (scaled)
        #pragma unroll
        for (int i = 0; i < 2; i++){
            #pragma unroll
            for (int j = 0; j < 2; j++){
                int col = cc*128 + w*16 + j*8 + 2*tg;
                float2 s0 = make_float2(acc[i][j][0]*0.125f, acc[i][j][1]*0.125f);
                float2 s1 = make_float2(acc[i][j][2]*0.125f, acc[i][j][3]*0.125f);
                *(float2*)&Ssm[(i*16 + g)*SST + col]     = s0;
                *(float2*)&Ssm[(i*16 + g + 8)*SST + col] = s1;
            }
        }
        __syncthreads();
    }

    // ---------------- softmax phase: warp w handles rows 4w..4w+3 ----------
    const int ts_v = ts_ptr[0];
    #pragma unroll 1
    for (int rr = 0; rr < 4; rr++){
        int rl = w*4 + rr;
        int grow = qrow0 + rl;
        float4 v4[8];
        #pragma unroll
        for (int it = 0; it < 8; it++)
            v4[it] = *(float4*)&Ssm[rl*SST + lane*4 + it*128];

        float m = -1e30f;
        #pragma unroll
        for (int it = 0; it < 8; it++)
            m = fmaxf(m, fmaxf(fmaxf(v4[it].x, v4[it].y), fmaxf(v4[it].z, v4[it].w)));
        m = warpMax(m);

        float4 e4[8]; float s = 0.f;
        #pragma unroll
        for (int it = 0; it < 8; it++){
            e4[it].x = __expf(v4[it].x - m); e4[it].y = __expf(v4[it].y - m);
            e4[it].z = __expf(v4[it].z - m); e4[it].w = __expf(v4[it].w - m);
            s += e4[it].x + e4[it].y + e4[it].z + e4[it].w;
        }
        s = warpSum(s);
        float inv = 1.0f / s;

        if (grow < 64){
            __nv_bfloat16* du = pu + (((size_t)(bh*64 + grow)) << 10);
            #pragma unroll
            for (int it = 0; it < 8; it++){
                float4 p = make_float4(e4[it].x*inv, e4[it].y*inv, e4[it].z*inv, e4[it].w*inv);
                st_bf16x4(du + lane*4 + it*128, p);
            }
        }

        __nv_bfloat16* dp = pb + (((size_t)bh) << 20) + (((size_t)grow) << 10);
        bool dob = (ts_v < 8) && (grow < 64);
        if (dob){
            if (lane < 16){
                float c0 = (float)(lane*4);
                v4[0].x += 0.1f / (fabsf((float)grow - c0)        + 1.0f);
                v4[0].y += 0.1f / (fabsf((float)grow - (c0+1.f))  + 1.0f);
                v4[0].z += 0.1f / (fabsf((float)grow - (c0+2.f))  + 1.0f);
                v4[0].w += 0.1f / (fabsf((float)grow - (c0+3.f))  + 1.0f);
            }
            float m2 = -1e30f;
            #pragma unroll
            for (int it = 0; it < 8; it++)
                m2 = fmaxf(m2, fmaxf(fmaxf(v4[it].x, v4[it].y), fmaxf(v4[it].z, v4[it].w)));
            m2 = warpMax(m2);
            float s2 = 0.f;
            #pragma unroll
            for (int it = 0; it < 8; it++){
                e4[it].x = __expf(v4[it].x - m2); e4[it].y = __expf(v4[it].y - m2);
                e4[it].z = __expf(v4[it].z - m2); e4[it].w = __expf(v4[it].w - m2);
                s2 += e4[it].x + e4[it].y + e4[it].z + e4[it].w;
            }
            s2 = warpSum(s2);
            float inv2 = 1.0f / s2;
            #pragma unroll
            for (int it = 0; it < 8; it++){
                float4 p = make_float4(e4[it].x*inv2, e4[it].y*inv2, e4[it].z*inv2, e4[it].w*inv2);
                st_bf16x4(dp + lane*4 + it*128, p);
            }
        } else {
            #pragma unroll
            for (int it = 0; it < 8; it++){
                float4 p = make_float4(e4[it].x*inv, e4[it].y*inv, e4[it].z*inv, e4[it].w*inv);
                st_bf16x4(dp + lane*4 + it*128, p);
            }
        }
    }
}

// =====================================================================
// PV: ctx[b,s,h*64+n] = probs(bf16) @ V(fp32->bf16)  — bf16 m16n8k16 MMA
// grid (8 mtiles, 64 bh), 256 threads
// =====================================================================
__global__ void __launch_bounds__(256)
pv_bf16(const __nv_bfloat16* __restrict__ P, const float* __restrict__ V,
        float* __restrict__ ctx)
{
    constexpr int BK = 32, SA = 40;     // smem stride in bf16 units
    __shared__ __nv_bfloat16 As[2][128*SA];
    __shared__ __nv_bfloat16 Vs[2][64*SA];

    const int bh = blockIdx.y;
    P   += (size_t)bh << 20;
    V   += (size_t)bh << 16;
    ctx += ((size_t)(bh >> 4) << 20) + (size_t)(bh & 15)*64;

    const int tid = threadIdx.x;
    const int lane = tid & 31, g = lane >> 2, tg = lane & 3;
    const int w = tid >> 5;
    const int wm = (w >> 1) * 32, wn = (w & 1) * 32;
    const int m0 = blockIdx.x * 128;

    auto loadA = [&](int buf, int k0){
        #pragma unroll
        for (int i = 0; i < 2; i++){
            int id = tid + i*256;
            int r = id >> 2, c8 = (id & 3) << 3;
            cpasync16(smem_u32(&As[buf][r*SA + c8]),
                      P + (((size_t)(m0 + r)) << 10) + k0 + c8);
        }
    };
    auto loadV = [&](int buf, int k0){
        #pragma unroll
        for (int i = 0; i < 2; i++){
            int id = tid + i*256;
            int k = id >> 4, n4 = (id & 15) << 2;
            float4 v = *(const float4*)(V + (((size_t)(k0 + k)) << 6) + n4);
            Vs[buf][(n4+0)*SA + k] = __float2bfloat16_rn(v.x);
            Vs[buf][(n4+1)*SA + k] = __float2bfloat16_rn(v.y);
            Vs[buf][(n4+2)*SA + k] = __float2bfloat16_rn(v.z);
            Vs[buf][(n4+3)*SA + k] = __float2bfloat16_rn(v.w);
        }
    };

    float acc[2][4][4];
    #pragma unroll
    for (int i=0;i<2;i++)
        #pragma unroll
        for (int j=0;j<4;j++)
            #pragma unroll
            for (int r=0;r<4;r++) acc[i][j][r]=0.f;

    loadA(0, 0);
    asm volatile("cp.async.commit_group;\n");
    loadV(0, 0);

    for (int it = 0; it < SS/BK; it++){
        int buf = it & 1;
        if (it + 1 < SS/BK){
            loadA(buf^1, (it+1)*BK);
            asm volatile("cp.async.commit_group;\n");
            loadV(buf^1, (it+1)*BK);
            asm volatile("cp.async.wait_group 1;\n");
        } else {
            asm volatile("cp.async.wait_group 0;\n");
        }
        __syncthreads();

        #pragma unroll
        for (int kk = 0; kk < 2; kk++){
            uint32_t af[2][4], bf[4][2];
            #pragma unroll
            for (int i = 0; i < 2; i++){
                const __nv_bfloat16* ap = &As[buf][(wm + i*16 + g)*SA + kk*16 + 2*tg];
                af[i][0] = *(const uint32_t*)(ap);
                af[i][1] = *(const uint32_t*)(ap + 8*SA);
                af[i][2] = *(const uint32_t*)(ap + 8);
                af[i][3] = *(const uint32_t*)(ap + 8*SA + 8);
            }
            #pragma unroll
            for (int j = 0; j < 4; j++){
                const __nv_bfloat16* bp = &Vs[buf][(wn + j*8 + g)*SA + kk*16 + 2*tg];
                bf[j][0] = *(const uint32_t*)(bp);
                bf[j][1] = *(const uint32_t*)(bp + 8);
            }
            #pragma unroll
            for (int i = 0; i < 2; i++)
                #pragma unroll
                for (int j = 0; j < 4; j++)
                    mma_bf16(acc[i][j], af[i], bf[j]);
        }
        __syncthreads();
    }

    #pragma unroll
    for (int i = 0; i < 2; i++){
        #pragma unroll
        for (int rr = 0; rr < 2; rr++){
            int row = m0 + wm + i*16 + g + rr*8;
            #pragma unroll
            for (int j = 0; j < 4; j++){
                int col = wn + j*8 + 2*tg;
                float2 o = make_float2(acc[i][j][rr*2+0], acc[i][j][rr*2+1]);
                *(float2*)&ctx[((size_t)row << 10) + col] = o;
            }
        }
    }
}

// ---------------- out2: head-mean of unbiased probs (fp32 accum) ------------
__global__ void __launch_bounds__(256)
out2_reduce(const __nv_bfloat16* __restrict__ pb, const __nv_bfloat16* __restrict__ pu,
            float* __restrict__ out2)
{
    const int b = blockIdx.y, row = blockIdx.x;
    const int tid = threadIdx.x;
    const int c0 = tid * 4;

    float4 acc = make_float4(0.f, 0.f, 0.f, 0.f);
    #pragma unroll 1
    for (int h = 0; h < NH; h++){
        const __nv_bfloat16* src = (row < 64)
            ? pu + ((((size_t)((b*NH + h)*64 + row))) << 10)
            : pb + (((size_t)(b*NH + h)) << 20) + (((size_t)row) << 10);
        uint2 u = *(const uint2*)(src + c0);
        __nv_bfloat162 lo = *reinterpret_cast<__nv_bfloat162*>(&u.x);
        __nv_bfloat162 hi = *reinterpret_cast<__nv_bfloat162*>(&u.y);
        acc.x += __bfloat162float(lo.x);  acc.y += __bfloat162float(lo.y);
        acc.z += __bfloat162float(hi.x);  acc.w += __bfloat162float(hi.y);
    }
    const float k = 1.0f / 16.0f;
    float4 o = make_float4(acc.x*k, acc.y*k, acc.z*k, acc.w*k);
    *(float4*)&out2[(((size_t)(b*SS + row)) << 10) + c0] = o;
}

// ---------------- LayerNorm --------------------------------------------------
__global__ void __launch_bounds__(256)
layernorm(const float* __restrict__ R, const float* __restrict__ gamma,
          const float* __restrict__ beta, float* __restrict__ out)
{
    __shared__ float red[8];
    int row = blockIdx.x;
    int tid = threadIdx.x;
    const float* src = R + ((size_t)row << 10);
    float v[4];
    #pragma unroll
    for (int j=0;j<4;j++) v[j] = src[tid + (j<<8)];
    float s = v[0]+v[1]+v[2]+v[3];
    s = blockSum(s, red);
    float mu = s * (1.0f/1024.0f);
    float q = 0.f;
    #pragma unroll
    for (int j=0;j<4;j++) { float d = v[j]-mu; q += d*d; }
    q = blockSum(q, red);
    float inv = rsqrtf(q * (1.0f/1024.0f) + 1e-5f);
    #pragma unroll
    for (int j=0;j<4;j++) {
        int c = tid + (j<<8);
        out[((size_t)row << 10) + c] = (v[j]-mu)*inv*gamma[c] + beta[c];
    }
}

// ---------------- launch -----------------------------------------------------
extern "C" void kernel_launch(void* const* d_in, const int* in_sizes, int n_in,
                              void* d_out, int out_size)
{
    const float* x  = (const float*)d_in[0];
    const int*   ts = (const int*)  d_in[1];
    const float* Wq = (const float*)d_in[2];
    const float* bq = (const float*)d_in[3];
    const float* Wk = (const float*)d_in[4];
    const float* bk = (const float*)d_in[5];
    const float* Wv = (const float*)d_in[6];
    const float* bv = (const float*)d_in[7];
    const float* Wo = (const float*)d_in[8];
    const float* bo = (const float*)d_in[9];
    const float* ga = (const float*)d_in[10];
    const float* be = (const float*)d_in[11];

    float* out1 = (float*)d_out;
    float* out2 = out1 + (size_t)BB*SS*DD;

    void *pq, *pk, *pv, *ppb, *ppu, *pctx, *pres;
    cudaGetSymbolAddress(&pq,  g_q);
    cudaGetSymbolAddress(&pk,  g_k);
    cudaGetSymbolAddress(&pv,  g_v);
    cudaGetSymbolAddress(&ppb, g_pb);
    cudaGetSymbolAddress(&ppu, g_pu);
    cudaGetSymbolAddress(&pctx,g_ctx);
    cudaGetSymbolAddress(&pres,g_res);

    auto kproj  = mma_gemm<0>;
    auto koproj = mma_gemm<2>;
    const int SM_BIG = 2*(128+128)*36*4;                 // 73728 B
    const int SM_FUS = (32*SST + 32*68 + 2*128*68)*4;    // 210432 B
    cudaFuncSetAttribute((const void*)kproj,  cudaFuncAttributeMaxDynamicSharedMemorySize, SM_BIG);
    cudaFuncSetAttribute((const void*)koproj, cudaFuncAttributeMaxDynamicSharedMemorySize, SM_BIG);
    cudaFuncSetAttribute((const void*)fused_qk_softmax, cudaFuncAttributeMaxDynamicSharedMemorySize, SM_FUS);

    dim3 blk(128);

    // QKV projections
    kproj<<<dim3(8,32), blk, SM_BIG>>>(x, Wq, bq, nullptr, (float*)pq, BB*SS, DD, DD);
    kproj<<<dim3(8,32), blk, SM_BIG>>>(x, Wk, bk, nullptr, (float*)pk, BB*SS, DD, DD);
    kproj<<<dim3(8,32), blk, SM_BIG>>>(x, Wv, bv, nullptr, (float*)pv, BB*SS, DD, DD);

    // Fused QK^T + softmax (biased probs bf16 + unbiased rows<64)
    fused_qk_softmax<<<dim3(32,16,4), 256, SM_FUS>>>(
        (const float*)pq, (const float*)pk,
        (__nv_bfloat16*)ppb, (__nv_bfloat16*)ppu, ts);

    // out2 = head-mean of unbiased probs
    out2_reduce<<<dim3(SS,BB), 256>>>((const __nv_bfloat16*)ppb,
                                      (const __nv_bfloat16*)ppu, out2);

    // ctx = probs @ V  (bf16 MMA)
    pv_bf16<<<dim3(8,BHN), 256>>>((const __nv_bfloat16*)ppb, (const float*)pv,
                                  (float*)pctx);

    // out projection + bias + residual
    koproj<<<dim3(8,32), blk, SM_BIG>>>((const float*)pctx, Wo, bo, x,
                                        (float*)pres, BB*SS, DD, DD);

    // LayerNorm -> output 1
    layernorm<<<dim3(BB*SS), 256>>>((const float*)pres, ga, be, out1);
}

// round 4
// speedup vs baseline: 3.8639x; 1.1546x over previous
#include <cuda_runtime.h>
#include <cuda_bf16.h>
#include <cstdint>
#include <math.h>

// Problem constants
#define BB 4
#define SS 1024
#define DD 1024
#define NH 16
#define DKH 64
#define BHN (BB*NH)   // 64

typedef __nv_bfloat16 bf16;

// ---------------- device scratch (no allocs allowed) ----------------
__device__ bf16  g_q[BB*NH*SS*DKH];                 // bf16 [b,h,s,dk], q pre-scaled by 0.125
__device__ bf16  g_k[BB*NH*SS*DKH];
__device__ bf16  g_v[BB*NH*SS*DKH];
__device__ bf16  g_s[(size_t)BHN*SS*SS];            // raw scores bf16, 128MB
__device__ bf16  g_pb[(size_t)BHN*SS*SS];           // biased probs bf16, 128MB
__device__ float g_ctx[BB*SS*DD];                   // [b,s,d] 16MB
__device__ float g_res[BB*SS*DD];                   // residual sum, 16MB

// ---------------- reductions ----------------
__device__ __forceinline__ float warpMax(float v){
    #pragma unroll
    for (int o=16;o;o>>=1) v = fmaxf(v, __shfl_xor_sync(0xffffffffu, v, o));
    return v;
}
__device__ __forceinline__ float warpSum(float v){
    #pragma unroll
    for (int o=16;o;o>>=1) v += __shfl_xor_sync(0xffffffffu, v, o);
    return v;
}
__device__ __forceinline__ float blockMax(float v, float* sh){
    v = warpMax(v);
    int w = threadIdx.x >> 5, l = threadIdx.x & 31;
    if (l == 0) sh[w] = v;
    __syncthreads();
    float r = sh[0];
    #pragma unroll
    for (int i=1;i<8;i++) r = fmaxf(r, sh[i]);
    __syncthreads();
    return r;
}
__device__ __forceinline__ float blockSum(float v, float* sh){
    v = warpSum(v);
    int w = threadIdx.x >> 5, l = threadIdx.x & 31;
    if (l == 0) sh[w] = v;
    __syncthreads();
    float r = sh[0];
    #pragma unroll
    for (int i=1;i<8;i++) r += sh[i];
    __syncthreads();
    return r;
}

// ---------------- tensor-core helpers ----------------
__device__ __forceinline__ void mma_tf32(float* d, const uint32_t* a, const uint32_t* b){
    asm volatile(
        "mma.sync.aligned.m16n8k8.row.col.f32.tf32.tf32.f32 "
        "{%0,%1,%2,%3}, {%4,%5,%6,%7}, {%8,%9}, {%0,%1,%2,%3};\n"
        : "+f"(d[0]), "+f"(d[1]), "+f"(d[2]), "+f"(d[3])
        : "r"(a[0]), "r"(a[1]), "r"(a[2]), "r"(a[3]),
          "r"(b[0]), "r"(b[1]));
}
__device__ __forceinline__ void mma_bf16(float* d, const uint32_t* a, const uint32_t* b){
    asm volatile(
        "mma.sync.aligned.m16n8k16.row.col.f32.bf16.bf16.f32 "
        "{%0,%1,%2,%3}, {%4,%5,%6,%7}, {%8,%9}, {%0,%1,%2,%3};\n"
        : "+f"(d[0]), "+f"(d[1]), "+f"(d[2]), "+f"(d[3])
        : "r"(a[0]), "r"(a[1]), "r"(a[2]), "r"(a[3]),
          "r"(b[0]), "r"(b[1]));
}
__device__ __forceinline__ void cpasync16(uint32_t s, const void* g){
    asm volatile("cp.async.cg.shared.global [%0], [%1], 16;\n" :: "r"(s), "l"(g));
}
__device__ __forceinline__ uint32_t smem_u32(const void* p){
    return (uint32_t)__cvta_generic_to_shared(p);
}
__device__ __forceinline__ uint32_t pack_bf16x2(float x, float y){
    __nv_bfloat162 a = __floats2bfloat162_rn(x, y);
    return *reinterpret_cast<uint32_t*>(&a);
}
__device__ __forceinline__ void st_bf16x4(bf16* dst, float4 p){
    uint2 u;
    u.x = pack_bf16x2(p.x, p.y);
    u.y = pack_bf16x2(p.z, p.w);
    *reinterpret_cast<uint2*>(dst) = u;
}

// =====================================================================
// tf32 GEMM for projections (fp32 A,B).
//  MODE 0: QKV proj -> bf16 head-layout scatter, (acc+bias)*scale
//  MODE 2: out proj -> fp32, + bias + residual (flat)
// =====================================================================
template<int MODE>
__global__ void __launch_bounds__(128)
mma_gemm(const float* __restrict__ A, const float* __restrict__ Bg,
         const float* __restrict__ bias, const float* __restrict__ resid,
         void* __restrict__ Cv, int M, int N, int K, float scale)
{
    constexpr int BM=128, BN=128, BK=32, S=36;
    constexpr int T=128, MT=4, NTL=8;

    extern __shared__ float sm[];
    float* As = sm;                 // [2][BM][S]
    float* Bs = sm + 2*BM*S;        // [2][BN][S]

    const int tid = threadIdx.x;
    const int bm0 = blockIdx.y*BM, bn0 = blockIdx.x*BN;

    auto loadA = [&](int buf, int k0){
        #pragma unroll
        for (int i = 0; i < 8; i++){
            int id = tid + i*T;
            int r = id >> 3, ks = (id & 7)*4;
            cpasync16(smem_u32(&As[buf*BM*S + r*S + ks]),
                      A + (size_t)(bm0 + r)*K + k0 + ks);
        }
    };
    auto loadB = [&](int buf, int k0){
        #pragma unroll
        for (int i = 0; i < 8; i++){
            int id = tid + i*T;
            int r = id >> 3, ks = (id & 7)*4;
            cpasync16(smem_u32(&Bs[buf*BN*S + r*S + ks]),
                      Bg + (size_t)(bn0 + r)*K + k0 + ks);
        }
    };

    const int lane = tid & 31, g = lane >> 2, tg = lane & 3;
    const int warp = tid >> 5;
    const int wm = (warp >> 1) * 64, wn = (warp & 1) * 64;

    float acc[MT][NTL][4];
    #pragma unroll
    for (int i=0;i<MT;i++)
        #pragma unroll
        for (int j=0;j<NTL;j++)
            #pragma unroll
            for (int r=0;r<4;r++) acc[i][j][r] = 0.f;

    const int nt = K / BK;
    loadA(0, 0); loadB(0, 0);
    asm volatile("cp.async.commit_group;\n");

    for (int it = 0; it < nt; it++){
        int buf = it & 1;
        if (it + 1 < nt) {
            loadA(buf^1, (it+1)*BK); loadB(buf^1, (it+1)*BK);
            asm volatile("cp.async.commit_group;\n");
            asm volatile("cp.async.wait_group 1;\n");
        } else {
            asm volatile("cp.async.wait_group 0;\n");
        }
        __syncthreads();

        const float* Ab = As + buf*BM*S;
        const float* Bb = Bs + buf*BN*S;
        #pragma unroll
        for (int c = 0; c < BK/8; c++){
            uint32_t af[MT][4], bf[NTL][2];
            #pragma unroll
            for (int i = 0; i < MT; i++){
                const float* ap = Ab + (wm + i*16 + g)*S + c*8 + tg;
                af[i][0] = __float_as_uint(ap[0]);
                af[i][1] = __float_as_uint(ap[8*S]);
                af[i][2] = __float_as_uint(ap[4]);
                af[i][3] = __float_as_uint(ap[8*S + 4]);
            }
            #pragma unroll
            for (int j = 0; j < NTL; j++){
                const float* bp = Bb + (wn + j*8 + g)*S + c*8 + tg;
                bf[j][0] = __float_as_uint(bp[0]);
                bf[j][1] = __float_as_uint(bp[4]);
            }
            #pragma unroll
            for (int i = 0; i < MT; i++)
                #pragma unroll
                for (int j = 0; j < NTL; j++)
                    mma_tf32(acc[i][j], af[i], bf[j]);
        }
        __syncthreads();
    }

    #pragma unroll
    for (int i = 0; i < MT; i++){
        #pragma unroll
        for (int rr = 0; rr < 2; rr++){
            int row = bm0 + wm + i*16 + g + rr*8;
            #pragma unroll
            for (int j = 0; j < NTL; j++){
                int col = bn0 + wn + j*8 + 2*tg;
                float vx = acc[i][j][rr*2 + 0];
                float vy = acc[i][j][rr*2 + 1];
                if (MODE == 0) {
                    vx = (vx + bias[col])   * scale;
                    vy = (vy + bias[col+1]) * scale;
                    int b = row >> 10, s = row & 1023;
                    int h = col >> 6, dd = col & 63;
                    bf16* C = (bf16*)Cv;
                    uint32_t u = pack_bf16x2(vx, vy);
                    *(uint32_t*)&C[((size_t)(b*NH + h) << 16) + s*DKH + dd] = u;
                } else {
                    float* C = (float*)Cv;
                    size_t idx = (size_t)row*N + col;
                    float2 r2 = *(const float2*)&resid[idx];
                    float2 o = make_float2(vx + bias[col] + r2.x,
                                           vy + bias[col+1] + r2.y);
                    *(float2*)&C[idx] = o;
                }
            }
        }
    }
}

// =====================================================================
// Scores: per-bh  S[1024,1024](bf16) = Qb(bf16, pre-scaled) @ Kb^T(bf16)
// 128x128 tiles, K=64 single-shot, 256 threads (2x4 warps, 64x32 warp tiles)
// =====================================================================
#define SCA 72   // bf16 smem stride (64 + 8 pad)
__global__ void __launch_bounds__(256)
scores_bf16(const bf16* __restrict__ Q, const bf16* __restrict__ K,
            bf16* __restrict__ Sc)
{
    __shared__ bf16 Qs[128*SCA];
    __shared__ bf16 Ks[128*SCA];

    const int bh = blockIdx.z;
    Q  += (size_t)bh << 16;
    K  += (size_t)bh << 16;
    Sc += (size_t)bh << 20;

    const int tid = threadIdx.x;
    const int bm0 = blockIdx.y*128, bn0 = blockIdx.x*128;

    #pragma unroll
    for (int i = 0; i < 4; i++){
        int id = tid + i*256;
        int r = id >> 3, c8 = (id & 7) << 3;
        cpasync16(smem_u32(&Qs[r*SCA + c8]), Q + (size_t)(bm0 + r)*DKH + c8);
    }
    #pragma unroll
    for (int i = 0; i < 4; i++){
        int id = tid + i*256;
        int r = id >> 3, c8 = (id & 7) << 3;
        cpasync16(smem_u32(&Ks[r*SCA + c8]), K + (size_t)(bn0 + r)*DKH + c8);
    }
    asm volatile("cp.async.commit_group;\n");
    asm volatile("cp.async.wait_group 0;\n");
    __syncthreads();

    const int lane = tid & 31, g = lane >> 2, tg = lane & 3;
    const int w = tid >> 5;
    const int wm = (w >> 2)*64, wn = (w & 3)*32;   // 2x4 warps

    float acc[4][4][4];
    #pragma unroll
    for (int i=0;i<4;i++)
        #pragma unroll
        for (int j=0;j<4;j++)
            #pragma unroll
            for (int r=0;r<4;r++) acc[i][j][r]=0.f;

    #pragma unroll
    for (int kk = 0; kk < 4; kk++){
        uint32_t af[4][4], bfr[4][2];
        #pragma unroll
        for (int i = 0; i < 4; i++){
            const bf16* ap = &Qs[(wm + i*16 + g)*SCA + kk*16 + 2*tg];
            af[i][0] = *(const uint32_t*)(ap);
            af[i][1] = *(const uint32_t*)(ap + 8*SCA);
            af[i][2] = *(const uint32_t*)(ap + 8);
            af[i][3] = *(const uint32_t*)(ap + 8*SCA + 8);
        }
        #pragma unroll
        for (int j = 0; j < 4; j++){
            const bf16* bp = &Ks[(wn + j*8 + g)*SCA + kk*16 + 2*tg];
            bfr[j][0] = *(const uint32_t*)(bp);
            bfr[j][1] = *(const uint32_t*)(bp + 8);
        }
        #pragma unroll
        for (int i = 0; i < 4; i++)
            #pragma unroll
            for (int j = 0; j < 4; j++)
                mma_bf16(acc[i][j], af[i], bfr[j]);
    }

    #pragma unroll
    for (int i = 0; i < 4; i++){
        #pragma unroll
        for (int rr = 0; rr < 2; rr++){
            int row = bm0 + wm + i*16 + g + rr*8;
            #pragma unroll
            for (int j = 0; j < 4; j++){
                int col = bn0 + wn + j*8 + 2*tg;
                uint32_t u = pack_bf16x2(acc[i][j][rr*2+0], acc[i][j][rr*2+1]);
                *(uint32_t*)&Sc[((size_t)row << 10) + col] = u;
            }
        }
    }
}

// =====================================================================
// Softmax over scores (bf16) per (b,row): loops 16 heads.
//  - biased probs -> pb (bf16)
//  - accumulates head-mean of UNbiased softmax -> out2 (fp32), written once
// =====================================================================
__global__ void __launch_bounds__(256)
softmax_all(const bf16* __restrict__ Sc, bf16* __restrict__ pb,
            float* __restrict__ out2, const int* __restrict__ ts_ptr)
{
    __shared__ float red[8];
    const int b   = blockIdx.y;
    const int row = blockIdx.x;
    const int tid = threadIdx.x;
    const int c0  = tid * 4;
    const bool dob = (ts_ptr[0] < 8) && (row < 64);

    float acc[4] = {0.f, 0.f, 0.f, 0.f};

    #pragma unroll 1
    for (int h = 0; h < NH; h++){
        size_t off = (((size_t)(b*NH + h)) << 20) + (((size_t)row) << 10) + c0;
        uint2 u = *(const uint2*)(Sc + off);
        __nv_bfloat162 lo = *reinterpret_cast<__nv_bfloat162*>(&u.x);
        __nv_bfloat162 hi = *reinterpret_cast<__nv_bfloat162*>(&u.y);
        float v[4] = { __bfloat162float(lo.x), __bfloat162float(lo.y),
                       __bfloat162float(hi.x), __bfloat162float(hi.y) };

        // unbiased softmax -> accumulate for out2
        float m = fmaxf(fmaxf(v[0], v[1]), fmaxf(v[2], v[3]));
        m = blockMax(m, red);
        float e[4], s = 0.f;
        #pragma unroll
        for (int j = 0; j < 4; j++){ e[j] = __expf(v[j] - m); s += e[j]; }
        s = blockSum(s, red);
        float inv = 1.0f / s;
        #pragma unroll
        for (int j = 0; j < 4; j++) acc[j] += e[j]*inv;

        bf16* dst = pb + off;
        if (dob){
            float vb[4];
            #pragma unroll
            for (int j = 0; j < 4; j++){
                int c = c0 + j;
                vb[j] = v[j] + ((c < 64) ? 0.1f / (fabsf((float)(row - c)) + 1.0f) : 0.f);
            }
            float m2 = fmaxf(fmaxf(vb[0], vb[1]), fmaxf(vb[2], vb[3]));
            m2 = blockMax(m2, red);
            float eb[4], s2 = 0.f;
            #pragma unroll
            for (int j = 0; j < 4; j++){ eb[j] = __expf(vb[j] - m2); s2 += eb[j]; }
            s2 = blockSum(s2, red);
            float inv2 = 1.0f / s2;
            st_bf16x4(dst, make_float4(eb[0]*inv2, eb[1]*inv2, eb[2]*inv2, eb[3]*inv2));
        } else {
            st_bf16x4(dst, make_float4(e[0]*inv, e[1]*inv, e[2]*inv, e[3]*inv));
        }
    }

    const float k = 1.0f / 16.0f;
    float4 o = make_float4(acc[0]*k, acc[1]*k, acc[2]*k, acc[3]*k);
    *(float4*)&out2[(((size_t)(b*SS + row)) << 10) + c0] = o;
}

// =====================================================================
// PV: ctx[b,s,h*64+n] = probs(bf16) @ V(bf16)  — bf16 m16n8k16 MMA
// grid (8 mtiles, 64 bh), 256 threads
// =====================================================================
__global__ void __launch_bounds__(256)
pv_bf16(const bf16* __restrict__ P, const bf16* __restrict__ V,
        float* __restrict__ ctx)
{
    constexpr int BK = 32, SA = 40;     // smem strides (bf16 units)
    __shared__ bf16 As[2][128*SA];
    __shared__ bf16 Vs[2][64*SA];

    const int bh = blockIdx.y;
    P   += (size_t)bh << 20;
    V   += (size_t)bh << 16;
    ctx += ((size_t)(bh >> 4) << 20) + (size_t)(bh & 15)*64;

    const int tid = threadIdx.x;
    const int lane = tid & 31, g = lane >> 2, tg = lane & 3;
    const int w = tid >> 5;
    const int wm = (w >> 1) * 32, wn = (w & 1) * 32;
    const int m0 = blockIdx.x * 128;

    auto loadA = [&](int buf, int k0){
        #pragma unroll
        for (int i = 0; i < 2; i++){
            int id = tid + i*256;
            int r = id >> 2, c8 = (id & 3) << 3;
            cpasync16(smem_u32(&As[buf][r*SA + c8]),
                      P + (((size_t)(m0 + r)) << 10) + k0 + c8);
        }
    };
    auto loadV = [&](int buf, int k0){
        int k  = tid & 31;
        int n8 = (tid >> 5) * 8;
        union { uint4 u; bf16 h[8]; } val;
        val.u = *(const uint4*)(V + (((size_t)(k0 + k)) << 6) + n8);
        #pragma unroll
        for (int t = 0; t < 8; t++)
            Vs[buf][(n8 + t)*SA + k] = val.h[t];
    };

    float acc[2][4][4];
    #pragma unroll
    for (int i=0;i<2;i++)
        #pragma unroll
        for (int j=0;j<4;j++)
            #pragma unroll
            for (int r=0;r<4;r++) acc[i][j][r]=0.f;

    loadA(0, 0);
    asm volatile("cp.async.commit_group;\n");
    loadV(0, 0);

    for (int it = 0; it < SS/BK; it++){
        int buf = it & 1;
        if (it + 1 < SS/BK){
            loadA(buf^1, (it+1)*BK);
            asm volatile("cp.async.commit_group;\n");
            loadV(buf^1, (it+1)*BK);
            asm volatile("cp.async.wait_group 1;\n");
        } else {
            asm volatile("cp.async.wait_group 0;\n");
        }
        __syncthreads();

        #pragma unroll
        for (int kk = 0; kk < 2; kk++){
            uint32_t af[2][4], bfr[4][2];
            #pragma unroll
            for (int i = 0; i < 2; i++){
                const bf16* ap = &As[buf][(wm + i*16 + g)*SA + kk*16 + 2*tg];
                af[i][0] = *(const uint32_t*)(ap);
                af[i][1] = *(const uint32_t*)(ap + 8*SA);
                af[i][2] = *(const uint32_t*)(ap + 8);
                af[i][3] = *(const uint32_t*)(ap + 8*SA + 8);
            }
            #pragma unroll
            for (int j = 0; j < 4; j++){
                const bf16* bp = &Vs[buf][(wn + j*8 + g)*SA + kk*16 + 2*tg];
                bfr[j][0] = *(const uint32_t*)(bp);
                bfr[j][1] = *(const uint32_t*)(bp + 8);
            }
            #pragma unroll
            for (int i = 0; i < 2; i++)
                #pragma unroll
                for (int j = 0; j < 4; j++)
                    mma_bf16(acc[i][j], af[i], bfr[j]);
        }
        __syncthreads();
    }

    #pragma unroll
    for (int i = 0; i < 2; i++){
        #pragma unroll
        for (int rr = 0; rr < 2; rr++){
            int row = m0 + wm + i*16 + g + rr*8;
            #pragma unroll
            for (int j = 0; j < 4; j++){
                int col = wn + j*8 + 2*tg;
                float2 o = make_float2(acc[i][j][rr*2+0], acc[i][j][rr*2+1]);
                *(float2*)&ctx[((size_t)row << 10) + col] = o;
            }
        }
    }
}

// ---------------- LayerNorm --------------------------------------------------
__global__ void __launch_bounds__(256)
layernorm(const float* __restrict__ R, const float* __restrict__ gamma,
          const float* __restrict__ beta, float* __restrict__ out)
{
    __shared__ float red[8];
    int row = blockIdx.x;
    int tid = threadIdx.x;
    const float* src = R + ((size_t)row << 10);
    float v[4];
    #pragma unroll
    for (int j=0;j<4;j++) v[j] = src[tid + (j<<8)];
    float s = v[0]+v[1]+v[2]+v[3];
    s = blockSum(s, red);
    float mu = s * (1.0f/1024.0f);
    float q = 0.f;
    #pragma unroll
    for (int j=0;j<4;j++) { float d = v[j]-mu; q += d*d; }
    q = blockSum(q, red);
    float inv = rsqrtf(q * (1.0f/1024.0f) + 1e-5f);
    #pragma unroll
    for (int j=0;j<4;j++) {
        int c = tid + (j<<8);
        out[((size_t)row << 10) + c] = (v[j]-mu)*inv*gamma[c] + beta[c];
    }
}

// ---------------- launch -----------------------------------------------------
extern "C" void kernel_launch(void* const* d_in, const int* in_sizes, int n_in,
                              void* d_out, int out_size)
{
    const float* x  = (const float*)d_in[0];
    const int*   ts = (const int*)  d_in[1];
    const float* Wq = (const float*)d_in[2];
    const float* bq = (const float*)d_in[3];
    const float* Wk = (const float*)d_in[4];
    const float* bk = (const float*)d_in[5];
    const float* Wv = (const float*)d_in[6];
    const float* bv = (const float*)d_in[7];
    const float* Wo = (const float*)d_in[8];
    const float* bo = (const float*)d_in[9];
    const float* ga = (const float*)d_in[10];
    const float* be = (const float*)d_in[11];

    float* out1 = (float*)d_out;
    float* out2 = out1 + (size_t)BB*SS*DD;

    void *pq, *pk, *pv, *psc, *ppb, *pctx, *pres;
    cudaGetSymbolAddress(&pq,  g_q);
    cudaGetSymbolAddress(&pk,  g_k);
    cudaGetSymbolAddress(&pv,  g_v);
    cudaGetSymbolAddress(&psc, g_s);
    cudaGetSymbolAddress(&ppb, g_pb);
    cudaGetSymbolAddress(&pctx,g_ctx);
    cudaGetSymbolAddress(&pres,g_res);

    auto kproj  = mma_gemm<0>;
    auto koproj = mma_gemm<2>;
    const int SM_BIG = 2*(128+128)*36*4;   // 73728 B
    cudaFuncSetAttribute((const void*)kproj,  cudaFuncAttributeMaxDynamicSharedMemorySize, SM_BIG);
    cudaFuncSetAttribute((const void*)koproj, cudaFuncAttributeMaxDynamicSharedMemorySize, SM_BIG);

    dim3 blk(128);

    // QKV projections -> bf16 head layout (q pre-scaled by 1/8)
    kproj<<<dim3(8,32), blk, SM_BIG>>>(x, Wq, bq, nullptr, pq, BB*SS, DD, DD, 0.125f);
    kproj<<<dim3(8,32), blk, SM_BIG>>>(x, Wk, bk, nullptr, pk, BB*SS, DD, DD, 1.0f);
    kproj<<<dim3(8,32), blk, SM_BIG>>>(x, Wv, bv, nullptr, pv, BB*SS, DD, DD, 1.0f);

    // Raw scores (bf16) per bh
    scores_bf16<<<dim3(8,8,BHN), 256>>>((const bf16*)pq, (const bf16*)pk,
                                        (bf16*)psc);

    // Softmax: biased probs -> pb, head-mean unbiased -> out2
    softmax_all<<<dim3(SS,BB), 256>>>((const bf16*)psc, (bf16*)ppb, out2, ts);

    // ctx = probs @ V
    pv_bf16<<<dim3(8,BHN), 256>>>((const bf16*)ppb, (const bf16*)pv, (float*)pctx);

    // out projection + bias + residual
    koproj<<<dim3(8,32), blk, SM_BIG>>>((const float*)pctx, Wo, bo, x,
                                        pres, BB*SS, DD, DD, 1.0f);

    // LayerNorm -> output 1
    layernorm<<<dim3(BB*SS), 256>>>((const float*)pres, ga, be, out1);
}